// round 2
// baseline (speedup 1.0000x reference)
#include <cuda_runtime.h>
#include <math.h>

#define Bv 2
#define Tv 2048
#define Cv 768
#define Hv 12
#define HDv 64
#define BTv 4096

// Scratch (device globals: no allocation allowed)
__device__ float g_Q[Bv*Hv*Tv*HDv];   // scaled by log(T)*qm
__device__ float g_K[Bv*Hv*Tv*HDv];
__device__ float g_V[Bv*Hv*Tv*HDv];
__device__ float g_Y[BTv*Cv];

// ---------------------------------------------------------------------------
// GEMM: C[4096,768] = A[4096,768] @ W[768,768]
// mode 0/1/2 (via blockIdx.z + mode_base): write to g_Q/g_K/g_V in [B,H,T,HD],
//   mode 0 scales columns by log(2048)*qm[d].
// mode 3: A = g_Y, write row-major to outp.
// Tiling: BM=128, BN=64, BK=16, 256 threads, 8x4 per-thread microtile.
// ---------------------------------------------------------------------------
__global__ __launch_bounds__(256) void gemm_kernel(
    const float* __restrict__ A,
    const float* __restrict__ Wq,
    const float* __restrict__ Wk,
    const float* __restrict__ Wv,
    const float* __restrict__ qm,
    float* __restrict__ outp,
    int mode_base)
{
    const int mode = mode_base + blockIdx.z;
    const float* W  = (mode == 0) ? Wq : (mode == 1) ? Wk : (mode == 2) ? Wv : Wq;
    const float* Ap = (mode == 3) ? (const float*)g_Y : A;

    __shared__ float As[16 * 132];  // [k][m], padded
    __shared__ float Bs[16 * 64];   // [k][n]

    const int tid = threadIdx.x;
    const int ty = tid >> 4;        // 0..15 -> rows ty*8..ty*8+7
    const int tx = tid & 15;        // 0..15 -> cols tx*4..tx*4+3
    const int m0 = blockIdx.x * 128;
    const int n0 = blockIdx.y * 64;

    float acc[8][4];
    #pragma unroll
    for (int i = 0; i < 8; i++)
        #pragma unroll
        for (int j = 0; j < 4; j++) acc[i][j] = 0.0f;

    for (int k0 = 0; k0 < 768; k0 += 16) {
        // Load A tile 128x16 (transposed into As[k][m])
        #pragma unroll
        for (int it = 0; it < 2; it++) {
            int i = tid + it * 256;          // float4 index 0..511
            int row = i >> 2;                // 0..127
            int c4  = i & 3;                 // 0..3
            float4 v = *(const float4*)(Ap + (size_t)(m0 + row) * 768 + k0 + c4 * 4);
            As[(c4 * 4 + 0) * 132 + row] = v.x;
            As[(c4 * 4 + 1) * 132 + row] = v.y;
            As[(c4 * 4 + 2) * 132 + row] = v.z;
            As[(c4 * 4 + 3) * 132 + row] = v.w;
        }
        // Load B tile 16x64
        {
            int row = tid >> 4;              // 0..15
            int c4  = tid & 15;              // 0..15
            float4 v = *(const float4*)(W + (size_t)(k0 + row) * 768 + n0 + c4 * 4);
            *(float4*)&Bs[row * 64 + c4 * 4] = v;
        }
        __syncthreads();

        #pragma unroll
        for (int kk = 0; kk < 16; kk++) {
            float4 a0 = *(float4*)&As[kk * 132 + ty * 8];
            float4 a1 = *(float4*)&As[kk * 132 + ty * 8 + 4];
            float4 b  = *(float4*)&Bs[kk * 64 + tx * 4];
            float av[8] = {a0.x, a0.y, a0.z, a0.w, a1.x, a1.y, a1.z, a1.w};
            float bv[4] = {b.x, b.y, b.z, b.w};
            #pragma unroll
            for (int i = 0; i < 8; i++)
                #pragma unroll
                for (int j = 0; j < 4; j++)
                    acc[i][j] += av[i] * bv[j];
        }
        __syncthreads();
    }

    const int col = n0 + tx * 4;
    if (mode == 3) {
        #pragma unroll
        for (int i = 0; i < 8; i++) {
            int row = m0 + ty * 8 + i;
            float4 v = make_float4(acc[i][0], acc[i][1], acc[i][2], acc[i][3]);
            *(float4*)(outp + (size_t)row * 768 + col) = v;
        }
    } else {
        float* dst = (mode == 0) ? g_Q : (mode == 1) ? g_K : g_V;
        const int h = col >> 6;
        const int d = col & 63;
        float s0 = 1.f, s1 = 1.f, s2 = 1.f, s3 = 1.f;
        if (mode == 0) {
            const float LT = 7.6246189861593985f;   // log(2048), as f32 like ref
            s0 = LT * qm[d];  s1 = LT * qm[d + 1];
            s2 = LT * qm[d + 2]; s3 = LT * qm[d + 3];
        }
        #pragma unroll
        for (int i = 0; i < 8; i++) {
            int row = m0 + ty * 8 + i;
            int bb = row >> 11;               // /2048
            int t  = row & 2047;
            float4 v = make_float4(acc[i][0] * s0, acc[i][1] * s1,
                                   acc[i][2] * s2, acc[i][3] * s3);
            *(float4*)(dst + ((size_t)((bb * Hv + h) * Tv + t)) * 64 + d) = v;
        }
    }
}

// ---------------------------------------------------------------------------
// Attention with streaming top-4. Block = (qtile of 64 queries, h, b),
// 256 threads = 16 query-groups (4 queries each) x 16 key-lanes (4 keys each).
// Single pass over causal K tiles; per-thread sorted top-4 (val,idx); bitonic
// merge across the 16 key-lanes; kth from merge-with-zeros; gather <=4 V rows.
// ---------------------------------------------------------------------------
__global__ __launch_bounds__(256) void attn_kernel()
{
    __shared__ float Qt[64 * 68];   // [d][q]
    __shared__ float Kt[64 * 68];   // [d][key]

    const int tid = threadIdx.x;
    const int qy = tid >> 4;        // 0..15
    const int kx = tid & 15;        // 0..15
    const int qt = 31 - (int)blockIdx.x;   // heavy tiles first
    const int h = blockIdx.y;
    const int b = blockIdx.z;
    const size_t bh = ((size_t)(b * Hv + h)) * Tv * 64;

    // Load Q tile transposed: Qt[d][q]
    #pragma unroll
    for (int it = 0; it < 4; it++) {
        int i = it * 256 + tid;     // float4 index 0..1023
        int qrow = i >> 4;          // 0..63
        int d4   = i & 15;          // 0..15
        float4 v = *(const float4*)(g_Q + bh + (size_t)(qt * 64 + qrow) * 64 + d4 * 4);
        Qt[(d4 * 4 + 0) * 68 + qrow] = v.x;
        Qt[(d4 * 4 + 1) * 68 + qrow] = v.y;
        Qt[(d4 * 4 + 2) * 68 + qrow] = v.z;
        Qt[(d4 * 4 + 3) * 68 + qrow] = v.w;
    }

    float tv[4][4];
    int   ti[4][4];
    #pragma unroll
    for (int q = 0; q < 4; q++)
        #pragma unroll
        for (int m = 0; m < 4; m++) { tv[q][m] = -3.0e38f; ti[q][m] = 0; }

    for (int kt = 0; kt <= qt; kt++) {
        __syncthreads();            // previous Kt reads done (also covers Qt stores)
        // Load K tile transposed: Kt[d][key]
        #pragma unroll
        for (int it = 0; it < 4; it++) {
            int i = it * 256 + tid;
            int krow = i >> 4;
            int d4   = i & 15;
            float4 v = *(const float4*)(g_K + bh + (size_t)(kt * 64 + krow) * 64 + d4 * 4);
            Kt[(d4 * 4 + 0) * 68 + krow] = v.x;
            Kt[(d4 * 4 + 1) * 68 + krow] = v.y;
            Kt[(d4 * 4 + 2) * 68 + krow] = v.z;
            Kt[(d4 * 4 + 3) * 68 + krow] = v.w;
        }
        __syncthreads();

        float acc[4][4];
        #pragma unroll
        for (int q = 0; q < 4; q++)
            #pragma unroll
            for (int j = 0; j < 4; j++) acc[q][j] = 0.0f;

        #pragma unroll 16
        for (int d = 0; d < 64; d++) {
            float4 q4 = *(float4*)&Qt[d * 68 + qy * 4];
            float4 k4 = *(float4*)&Kt[d * 68 + kx * 4];
            float qa[4] = {q4.x, q4.y, q4.z, q4.w};
            float ka[4] = {k4.x, k4.y, k4.z, k4.w};
            #pragma unroll
            for (int q = 0; q < 4; q++)
                #pragma unroll
                for (int j = 0; j < 4; j++)
                    acc[q][j] += qa[q] * ka[j];
        }

        // Top-4 insert (sorted desc), causal mask j <= i
        #pragma unroll
        for (int q = 0; q < 4; q++) {
            int iglob = qt * 64 + qy * 4 + q;
            #pragma unroll
            for (int j = 0; j < 4; j++) {
                int jglob = kt * 64 + kx * 4 + j;
                float s = acc[q][j] * 0.125f;    // 1/sqrt(64), applied like ref
                if (jglob <= iglob && s > tv[q][3]) {
                    if (s > tv[q][1]) {
                        tv[q][3] = tv[q][2]; ti[q][3] = ti[q][2];
                        tv[q][2] = tv[q][1]; ti[q][2] = ti[q][1];
                        if (s > tv[q][0]) {
                            tv[q][1] = tv[q][0]; ti[q][1] = ti[q][0];
                            tv[q][0] = s; ti[q][0] = jglob;
                        } else { tv[q][1] = s; ti[q][1] = jglob; }
                    } else {
                        if (s > tv[q][2]) {
                            tv[q][3] = tv[q][2]; ti[q][3] = ti[q][2];
                            tv[q][2] = s; ti[q][2] = jglob;
                        } else { tv[q][3] = s; ti[q][3] = jglob; }
                    }
                }
            }
        }
    }

    // Merge top-4 across the 16 key-lanes (bitonic half-clean + sort-4)
    #pragma unroll
    for (int msk = 1; msk <= 8; msk <<= 1) {
        #pragma unroll
        for (int q = 0; q < 4; q++) {
            float bvv[4]; int bii[4];
            #pragma unroll
            for (int r = 0; r < 4; r++) {
                bvv[r] = __shfl_xor_sync(0xffffffffu, tv[q][r], msk);
                bii[r] = __shfl_xor_sync(0xffffffffu, ti[q][r], msk);
            }
            float mv[4]; int mi[4];
            #pragma unroll
            for (int r = 0; r < 4; r++) {
                bool ta = tv[q][r] >= bvv[3 - r];
                mv[r] = ta ? tv[q][r] : bvv[3 - r];
                mi[r] = ta ? ti[q][r] : bii[3 - r];
            }
            // sort bitonic sequence desc: CE(0,2),(1,3),(0,1),(2,3)
            #define CEPAIR(x, y) do { if (mv[x] < mv[y]) { float tf = mv[x]; mv[x] = mv[y]; mv[y] = tf; int tn = mi[x]; mi[x] = mi[y]; mi[y] = tn; } } while (0)
            CEPAIR(0, 2); CEPAIR(1, 3); CEPAIR(0, 1); CEPAIR(2, 3);
            #undef CEPAIR
            #pragma unroll
            for (int r = 0; r < 4; r++) { tv[q][r] = mv[r]; ti[q][r] = mi[r]; }
        }
    }

    // kth (merged with T-(i+1) zeros), tanh, gather V, write Y
    #pragma unroll
    for (int q = 0; q < 4; q++) {
        int iglob = qt * 64 + qy * 4 + q;
        int nz = Tv - (iglob + 1);
        int p = (tv[q][0] > 0.f) + (tv[q][1] > 0.f) + (tv[q][2] > 0.f) + (tv[q][3] > 0.f);
        float kth;
        if (p >= 4) kth = tv[q][3];
        else if (nz >= 4 - p) kth = 0.0f;
        else {
            int ix = 3 - nz;
            kth = (ix == 0) ? tv[q][0] : (ix == 1) ? tv[q][1] : (ix == 2) ? tv[q][2] : tv[q][3];
        }
        float a0 = 0.f, a1 = 0.f, a2 = 0.f, a3 = 0.f;
        #pragma unroll
        for (int m = 0; m < 4; m++) {
            float val = tv[q][m];
            if (val >= kth && val > -1.0e37f) {
                float w = tanhf(val);
                float4 vv = *(const float4*)(g_V + bh + (size_t)ti[q][m] * 64 + kx * 4);
                a0 += w * vv.x; a1 += w * vv.y; a2 += w * vv.z; a3 += w * vv.w;
            }
        }
        float4 o = make_float4(a0, a1, a2, a3);
        *(float4*)(g_Y + (size_t)(b * Tv + iglob) * Cv + h * 64 + kx * 4) = o;
    }
}

// ---------------------------------------------------------------------------
extern "C" void kernel_launch(void* const* d_in, const int* in_sizes, int n_in,
                              void* d_out, int out_size)
{
    (void)in_sizes; (void)n_in; (void)out_size;
    const float* x  = (const float*)d_in[0];
    const float* Wq = (const float*)d_in[1];
    const float* Wk = (const float*)d_in[2];
    const float* Wv = (const float*)d_in[3];
    const float* Wp = (const float*)d_in[4];
    const float* qm = (const float*)d_in[5];
    float* out = (float*)d_out;

    dim3 blk(256);
    // QKV projections (Q scaled by log(T)*qm at epilogue), layout [B,H,T,HD]
    gemm_kernel<<<dim3(32, 12, 3), blk>>>(x, Wq, Wk, Wv, qm, nullptr, 0);
    // Streaming top-4 causal attention -> g_Y [B,T,C]
    attn_kernel<<<dim3(32, 12, 2), blk>>>();
    // Output projection
    gemm_kernel<<<dim3(32, 12, 1), blk>>>(nullptr, Wp, Wp, Wp, qm, out, 3);
}

// round 3
// speedup vs baseline: 1.0048x; 1.0048x over previous
#include <cuda_runtime.h>
#include <math.h>

#define Bv 2
#define Tv 2048
#define Cv 768
#define Hv 12
#define HDv 64
#define BTv 4096

// Scratch (device globals: no allocation allowed)
__device__ float g_Q[Bv*Hv*Tv*HDv];   // scaled by log(T)*qm
__device__ float g_K[Bv*Hv*Tv*HDv];
__device__ float g_V[Bv*Hv*Tv*HDv];
__device__ float g_Y[BTv*Cv];

// ---------------------------------------------------------------------------
// GEMM: C[4096,768] = A[4096,768] @ W[768,768]
// mode 0/1/2 (via blockIdx.z + mode_base): write to g_Q/g_K/g_V in [B,H,T,HD],
//   mode 0 scales columns by log(2048)*qm[d].
// mode 3: A = g_Y, write row-major to outp.
// Tiling: BM=128, BN=64, BK=16, 256 threads, 8x4 per-thread microtile.
// ---------------------------------------------------------------------------
__global__ __launch_bounds__(256) void gemm_kernel(
    const float* __restrict__ A,
    const float* __restrict__ Wq,
    const float* __restrict__ Wk,
    const float* __restrict__ Wv,
    const float* __restrict__ qm,
    float* __restrict__ outp,
    int mode_base)
{
    const int mode = mode_base + blockIdx.z;
    const float* W  = (mode == 0) ? Wq : (mode == 1) ? Wk : (mode == 2) ? Wv : Wq;
    const float* Ap = (mode == 3) ? (const float*)g_Y : A;

    __shared__ float As[16 * 132];  // [k][m], padded
    __shared__ float Bs[16 * 64];   // [k][n]

    const int tid = threadIdx.x;
    const int ty = tid >> 4;        // 0..15 -> rows ty*8..ty*8+7
    const int tx = tid & 15;        // 0..15 -> cols tx*4..tx*4+3
    const int m0 = blockIdx.x * 128;
    const int n0 = blockIdx.y * 64;

    float acc[8][4];
    #pragma unroll
    for (int i = 0; i < 8; i++)
        #pragma unroll
        for (int j = 0; j < 4; j++) acc[i][j] = 0.0f;

    for (int k0 = 0; k0 < 768; k0 += 16) {
        // Load A tile 128x16 (transposed into As[k][m])
        #pragma unroll
        for (int it = 0; it < 2; it++) {
            int i = tid + it * 256;          // float4 index 0..511
            int row = i >> 2;                // 0..127
            int c4  = i & 3;                 // 0..3
            float4 v = *(const float4*)(Ap + (size_t)(m0 + row) * 768 + k0 + c4 * 4);
            As[(c4 * 4 + 0) * 132 + row] = v.x;
            As[(c4 * 4 + 1) * 132 + row] = v.y;
            As[(c4 * 4 + 2) * 132 + row] = v.z;
            As[(c4 * 4 + 3) * 132 + row] = v.w;
        }
        // Load B tile 16x64
        {
            int row = tid >> 4;              // 0..15
            int c4  = tid & 15;              // 0..15
            float4 v = *(const float4*)(W + (size_t)(k0 + row) * 768 + n0 + c4 * 4);
            *(float4*)&Bs[row * 64 + c4 * 4] = v;
        }
        __syncthreads();

        #pragma unroll
        for (int kk = 0; kk < 16; kk++) {
            float4 a0 = *(float4*)&As[kk * 132 + ty * 8];
            float4 a1 = *(float4*)&As[kk * 132 + ty * 8 + 4];
            float4 b  = *(float4*)&Bs[kk * 64 + tx * 4];
            float av[8] = {a0.x, a0.y, a0.z, a0.w, a1.x, a1.y, a1.z, a1.w};
            float bv[4] = {b.x, b.y, b.z, b.w};
            #pragma unroll
            for (int i = 0; i < 8; i++)
                #pragma unroll
                for (int j = 0; j < 4; j++)
                    acc[i][j] += av[i] * bv[j];
        }
        __syncthreads();
    }

    const int col = n0 + tx * 4;
    if (mode == 3) {
        #pragma unroll
        for (int i = 0; i < 8; i++) {
            int row = m0 + ty * 8 + i;
            float4 v = make_float4(acc[i][0], acc[i][1], acc[i][2], acc[i][3]);
            *(float4*)(outp + (size_t)row * 768 + col) = v;
        }
    } else {
        float* dst = (mode == 0) ? g_Q : (mode == 1) ? g_K : g_V;
        const int h = col >> 6;
        const int d = col & 63;
        float s0 = 1.f, s1 = 1.f, s2 = 1.f, s3 = 1.f;
        if (mode == 0) {
            const float LT = 7.6246189861593985f;   // log(2048), as f32 like ref
            s0 = LT * qm[d];  s1 = LT * qm[d + 1];
            s2 = LT * qm[d + 2]; s3 = LT * qm[d + 3];
        }
        #pragma unroll
        for (int i = 0; i < 8; i++) {
            int row = m0 + ty * 8 + i;
            int bb = row >> 11;               // /2048
            int t  = row & 2047;
            float4 v = make_float4(acc[i][0] * s0, acc[i][1] * s1,
                                   acc[i][2] * s2, acc[i][3] * s3);
            *(float4*)(dst + ((size_t)((bb * Hv + h) * Tv + t)) * 64 + d) = v;
        }
    }
}

// ---------------------------------------------------------------------------
// Attention with streaming top-4. Block = (qtile of 64 queries, h, b),
// 256 threads = 16 query-groups (4 queries each) x 16 key-lanes (4 keys each).
// Single pass over causal K tiles; per-thread sorted top-4 (val,idx); bitonic
// merge across the 16 key-lanes; kth from merge-with-zeros; gather <=4 V rows.
// ---------------------------------------------------------------------------
__global__ __launch_bounds__(256) void attn_kernel()
{
    __shared__ float Qt[64 * 68];   // [d][q]
    __shared__ float Kt[64 * 68];   // [d][key]

    const int tid = threadIdx.x;
    const int qy = tid >> 4;        // 0..15
    const int kx = tid & 15;        // 0..15
    const int qt = 31 - (int)blockIdx.x;   // heavy tiles first
    const int h = blockIdx.y;
    const int b = blockIdx.z;
    const size_t bh = ((size_t)(b * Hv + h)) * Tv * 64;

    // Load Q tile transposed: Qt[d][q]
    #pragma unroll
    for (int it = 0; it < 4; it++) {
        int i = it * 256 + tid;     // float4 index 0..1023
        int qrow = i >> 4;          // 0..63
        int d4   = i & 15;          // 0..15
        float4 v = *(const float4*)(g_Q + bh + (size_t)(qt * 64 + qrow) * 64 + d4 * 4);
        Qt[(d4 * 4 + 0) * 68 + qrow] = v.x;
        Qt[(d4 * 4 + 1) * 68 + qrow] = v.y;
        Qt[(d4 * 4 + 2) * 68 + qrow] = v.z;
        Qt[(d4 * 4 + 3) * 68 + qrow] = v.w;
    }

    float tv[4][4];
    int   ti[4][4];
    #pragma unroll
    for (int q = 0; q < 4; q++)
        #pragma unroll
        for (int m = 0; m < 4; m++) { tv[q][m] = -3.0e38f; ti[q][m] = 0; }

    for (int kt = 0; kt <= qt; kt++) {
        __syncthreads();            // previous Kt reads done (also covers Qt stores)
        // Load K tile transposed: Kt[d][key]
        #pragma unroll
        for (int it = 0; it < 4; it++) {
            int i = it * 256 + tid;
            int krow = i >> 4;
            int d4   = i & 15;
            float4 v = *(const float4*)(g_K + bh + (size_t)(kt * 64 + krow) * 64 + d4 * 4);
            Kt[(d4 * 4 + 0) * 68 + krow] = v.x;
            Kt[(d4 * 4 + 1) * 68 + krow] = v.y;
            Kt[(d4 * 4 + 2) * 68 + krow] = v.z;
            Kt[(d4 * 4 + 3) * 68 + krow] = v.w;
        }
        __syncthreads();

        float acc[4][4];
        #pragma unroll
        for (int q = 0; q < 4; q++)
            #pragma unroll
            for (int j = 0; j < 4; j++) acc[q][j] = 0.0f;

        #pragma unroll 16
        for (int d = 0; d < 64; d++) {
            float4 q4 = *(float4*)&Qt[d * 68 + qy * 4];
            float4 k4 = *(float4*)&Kt[d * 68 + kx * 4];
            float qa[4] = {q4.x, q4.y, q4.z, q4.w};
            float ka[4] = {k4.x, k4.y, k4.z, k4.w};
            #pragma unroll
            for (int q = 0; q < 4; q++)
                #pragma unroll
                for (int j = 0; j < 4; j++)
                    acc[q][j] += qa[q] * ka[j];
        }

        // Top-4 insert (sorted desc), causal mask j <= i
        #pragma unroll
        for (int q = 0; q < 4; q++) {
            int iglob = qt * 64 + qy * 4 + q;
            #pragma unroll
            for (int j = 0; j < 4; j++) {
                int jglob = kt * 64 + kx * 4 + j;
                float s = acc[q][j] * 0.125f;    // 1/sqrt(64), applied like ref
                if (jglob <= iglob && s > tv[q][3]) {
                    if (s > tv[q][1]) {
                        tv[q][3] = tv[q][2]; ti[q][3] = ti[q][2];
                        tv[q][2] = tv[q][1]; ti[q][2] = ti[q][1];
                        if (s > tv[q][0]) {
                            tv[q][1] = tv[q][0]; ti[q][1] = ti[q][0];
                            tv[q][0] = s; ti[q][0] = jglob;
                        } else { tv[q][1] = s; ti[q][1] = jglob; }
                    } else {
                        if (s > tv[q][2]) {
                            tv[q][3] = tv[q][2]; ti[q][3] = ti[q][2];
                            tv[q][2] = s; ti[q][2] = jglob;
                        } else { tv[q][3] = s; ti[q][3] = jglob; }
                    }
                }
            }
        }
    }

    // Merge top-4 across the 16 key-lanes (bitonic half-clean + sort-4)
    #pragma unroll
    for (int msk = 1; msk <= 8; msk <<= 1) {
        #pragma unroll
        for (int q = 0; q < 4; q++) {
            float bvv[4]; int bii[4];
            #pragma unroll
            for (int r = 0; r < 4; r++) {
                bvv[r] = __shfl_xor_sync(0xffffffffu, tv[q][r], msk);
                bii[r] = __shfl_xor_sync(0xffffffffu, ti[q][r], msk);
            }
            float mv[4]; int mi[4];
            #pragma unroll
            for (int r = 0; r < 4; r++) {
                bool ta = tv[q][r] >= bvv[3 - r];
                mv[r] = ta ? tv[q][r] : bvv[3 - r];
                mi[r] = ta ? ti[q][r] : bii[3 - r];
            }
            // sort bitonic sequence desc: CE(0,2),(1,3),(0,1),(2,3)
            #define CEPAIR(x, y) do { if (mv[x] < mv[y]) { float tf = mv[x]; mv[x] = mv[y]; mv[y] = tf; int tn = mi[x]; mi[x] = mi[y]; mi[y] = tn; } } while (0)
            CEPAIR(0, 2); CEPAIR(1, 3); CEPAIR(0, 1); CEPAIR(2, 3);
            #undef CEPAIR
            #pragma unroll
            for (int r = 0; r < 4; r++) { tv[q][r] = mv[r]; ti[q][r] = mi[r]; }
        }
    }

    // kth (merged with T-(i+1) zeros), tanh, gather V, write Y
    #pragma unroll
    for (int q = 0; q < 4; q++) {
        int iglob = qt * 64 + qy * 4 + q;
        int nz = Tv - (iglob + 1);
        int p = (tv[q][0] > 0.f) + (tv[q][1] > 0.f) + (tv[q][2] > 0.f) + (tv[q][3] > 0.f);
        float kth;
        if (p >= 4) kth = tv[q][3];
        else if (nz >= 4 - p) kth = 0.0f;
        else {
            int ix = 3 - nz;
            kth = (ix == 0) ? tv[q][0] : (ix == 1) ? tv[q][1] : (ix == 2) ? tv[q][2] : tv[q][3];
        }
        float a0 = 0.f, a1 = 0.f, a2 = 0.f, a3 = 0.f;
        #pragma unroll
        for (int m = 0; m < 4; m++) {
            float val = tv[q][m];
            if (val >= kth && val > -1.0e37f) {
                float w = tanhf(val);
                float4 vv = *(const float4*)(g_V + bh + (size_t)ti[q][m] * 64 + kx * 4);
                a0 += w * vv.x; a1 += w * vv.y; a2 += w * vv.z; a3 += w * vv.w;
            }
        }
        float4 o = make_float4(a0, a1, a2, a3);
        *(float4*)(g_Y + (size_t)(b * Tv + iglob) * Cv + h * 64 + kx * 4) = o;
    }
}

// ---------------------------------------------------------------------------
extern "C" void kernel_launch(void* const* d_in, const int* in_sizes, int n_in,
                              void* d_out, int out_size)
{
    (void)in_sizes; (void)n_in; (void)out_size;
    const float* x  = (const float*)d_in[0];
    const float* Wq = (const float*)d_in[1];
    const float* Wk = (const float*)d_in[2];
    const float* Wv = (const float*)d_in[3];
    const float* Wp = (const float*)d_in[4];
    const float* qm = (const float*)d_in[5];
    float* out = (float*)d_out;

    dim3 blk(256);
    // QKV projections (Q scaled by log(T)*qm at epilogue), layout [B,H,T,HD]
    gemm_kernel<<<dim3(32, 12, 3), blk>>>(x, Wq, Wk, Wv, qm, nullptr, 0);
    // Streaming top-4 causal attention -> g_Y [B,T,C]
    attn_kernel<<<dim3(32, 12, 2), blk>>>();
    // Output projection
    gemm_kernel<<<dim3(32, 12, 1), blk>>>(nullptr, Wp, Wp, Wp, qm, out, 3);
}

// round 4
// speedup vs baseline: 1.1363x; 1.1308x over previous
#include <cuda_runtime.h>
#include <math.h>
#include <stdint.h>

#define Bv 2
#define Tv 2048
#define Cv 768
#define Hv 12
#define BTv 4096
typedef unsigned long long ull;

__device__ float g_Q[Bv*Hv*Tv*64];
__device__ float g_K[Bv*Hv*Tv*64];
__device__ float g_V[Bv*Hv*Tv*64];
__device__ float g_Y[BTv*Cv];

__device__ __forceinline__ ull pk2(float lo, float hi) {
    ull r; asm("mov.b64 %0, {%1, %2};" : "=l"(r) : "f"(lo), "f"(hi)); return r;
}
__device__ __forceinline__ void fma2(ull& d, ull a, ull b) {
    asm("fma.rn.f32x2 %0, %1, %2, %3;" : "=l"(d) : "l"(a), "l"(b), "l"(d));
}
__device__ __forceinline__ void upk(ull p, float& lo, float& hi) {
    asm("mov.b64 {%0, %1}, %2;" : "=f"(lo), "=f"(hi) : "l"(p));
}

// ---------------------------------------------------------------------------
// GEMM C[4096,768] = A @ W.  BM=128 BN=128 BK=16, 256 thr, 8x8 microtile
// via f32x2.  modes 0/1/2 scatter to g_Q/g_K/g_V [b,h,t,d] (0: *log(T)*qm);
// mode 3: A=g_Y -> outp row-major.
// ---------------------------------------------------------------------------
__global__ __launch_bounds__(256, 2) void gemm_kernel(
    const float* __restrict__ A, const float* __restrict__ Wq,
    const float* __restrict__ Wk, const float* __restrict__ Wv,
    const float* __restrict__ qm, float* __restrict__ outp, int mode_base)
{
    __shared__ float As[2][16*132];   // [k][m]
    __shared__ float Bs[2][16*132];   // [k][n]

    const int mode = mode_base + blockIdx.z;
    const float* W  = (mode == 0) ? Wq : (mode == 1) ? Wk : (mode == 2) ? Wv : Wq;
    const float* Ap = (mode == 3) ? (const float*)g_Y : A;

    const int tid = threadIdx.x;
    const int ty = tid >> 4, tx = tid & 15;
    const int m0 = blockIdx.x * 128, n0 = blockIdx.y * 128;

    const int arow = tid >> 2, ac4 = tid & 3;      // A: 2 rows (arow, arow+64)
    const int brow = tid >> 5, bc4 = tid & 31;     // B: 2 rows (brow, brow+8)
    const float* aG = Ap + (size_t)(m0 + arow) * 768 + ac4 * 4;
    const float* bG = W + (size_t)brow * 768 + n0 + bc4 * 4;

    ull acc2[8][4];
    #pragma unroll
    for (int r = 0; r < 8; r++)
        #pragma unroll
        for (int c = 0; c < 4; c++) acc2[r][c] = 0ull;

    float4 ra0 = *(const float4*)aG;
    float4 ra1 = *(const float4*)(aG + (size_t)64 * 768);
    float4 rb0 = *(const float4*)bG;
    float4 rb1 = *(const float4*)(bG + (size_t)8 * 768);

    #pragma unroll 1
    for (int kt = 0; kt < 48; kt++) {
        {   // store staged regs into buffer kt&1
            float* as = As[kt & 1]; float* bs = Bs[kt & 1];
            as[(ac4*4+0)*132 + arow] = ra0.x; as[(ac4*4+1)*132 + arow] = ra0.y;
            as[(ac4*4+2)*132 + arow] = ra0.z; as[(ac4*4+3)*132 + arow] = ra0.w;
            as[(ac4*4+0)*132 + arow+64] = ra1.x; as[(ac4*4+1)*132 + arow+64] = ra1.y;
            as[(ac4*4+2)*132 + arow+64] = ra1.z; as[(ac4*4+3)*132 + arow+64] = ra1.w;
            *(float4*)&bs[brow*132 + bc4*4] = rb0;
            *(float4*)&bs[(brow+8)*132 + bc4*4] = rb1;
        }
        __syncthreads();
        if (kt < 47) {   // prefetch next tile to regs
            ra0 = *(const float4*)(aG + (kt+1)*16);
            ra1 = *(const float4*)(aG + (size_t)64*768 + (kt+1)*16);
            rb0 = *(const float4*)(bG + (size_t)(kt+1)*16*768);
            rb1 = *(const float4*)(bG + (size_t)(kt+1)*16*768 + (size_t)8*768);
        }
        const float* as = As[kt & 1]; const float* bs = Bs[kt & 1];
        #pragma unroll
        for (int kk = 0; kk < 16; kk++) {
            float4 a0 = *(const float4*)&as[kk*132 + ty*8];
            float4 a1 = *(const float4*)&as[kk*132 + ty*8 + 4];
            ulonglong2 b0 = *(const ulonglong2*)&bs[kk*132 + tx*4];
            ulonglong2 b1 = *(const ulonglong2*)&bs[kk*132 + 64 + tx*4];
            ull ad[8] = { pk2(a0.x,a0.x), pk2(a0.y,a0.y), pk2(a0.z,a0.z), pk2(a0.w,a0.w),
                          pk2(a1.x,a1.x), pk2(a1.y,a1.y), pk2(a1.z,a1.z), pk2(a1.w,a1.w) };
            #pragma unroll
            for (int r = 0; r < 8; r++) {
                fma2(acc2[r][0], ad[r], b0.x);
                fma2(acc2[r][1], ad[r], b0.y);
                fma2(acc2[r][2], ad[r], b1.x);
                fma2(acc2[r][3], ad[r], b1.y);
            }
        }
        __syncthreads();
    }

    float accf[8][8];
    #pragma unroll
    for (int r = 0; r < 8; r++) {
        upk(acc2[r][0], accf[r][0], accf[r][1]);
        upk(acc2[r][1], accf[r][2], accf[r][3]);
        upk(acc2[r][2], accf[r][4], accf[r][5]);
        upk(acc2[r][3], accf[r][6], accf[r][7]);
    }

    if (mode == 3) {
        #pragma unroll
        for (int r = 0; r < 8; r++) {
            int row = m0 + ty*8 + r;
            *(float4*)(outp + (size_t)row*768 + n0 + tx*4) =
                make_float4(accf[r][0], accf[r][1], accf[r][2], accf[r][3]);
            *(float4*)(outp + (size_t)row*768 + n0 + 64 + tx*4) =
                make_float4(accf[r][4], accf[r][5], accf[r][6], accf[r][7]);
        }
    } else {
        float* dst = (mode == 0) ? g_Q : (mode == 1) ? g_K : g_V;
        const int h0 = n0 >> 6, d0 = tx*4;
        float s0 = 1.f, s1 = 1.f, s2 = 1.f, s3 = 1.f;
        if (mode == 0) {
            const float LT = 7.6246189861593985f;   // log(2048)
            s0 = LT*qm[d0]; s1 = LT*qm[d0+1]; s2 = LT*qm[d0+2]; s3 = LT*qm[d0+3];
        }
        #pragma unroll
        for (int r = 0; r < 8; r++) {
            int row = m0 + ty*8 + r;
            int bb = row >> 11, t = row & 2047;
            size_t p0 = ((size_t)(bb*Hv + h0)*Tv + t)*64 + d0;
            size_t p1 = ((size_t)(bb*Hv + h0 + 1)*Tv + t)*64 + d0;
            *(float4*)(dst + p0) = make_float4(accf[r][0]*s0, accf[r][1]*s1,
                                               accf[r][2]*s2, accf[r][3]*s3);
            *(float4*)(dst + p1) = make_float4(accf[r][4]*s0, accf[r][5]*s1,
                                               accf[r][6]*s2, accf[r][7]*s3);
        }
    }
}

// ---------------------------------------------------------------------------
// Attention: identical to the passing R2 kernel except the QK inner product
// uses f32x2 packed FMAs.
// ---------------------------------------------------------------------------
__global__ __launch_bounds__(256) void attn_kernel()
{
    __shared__ float Qt[64 * 68];   // [d][q]
    __shared__ float Kt[64 * 68];   // [d][key]

    const int tid = threadIdx.x;
    const int qy = tid >> 4, kx = tid & 15;
    const int qt = 31 - (int)blockIdx.x;
    const int h = blockIdx.y, b = blockIdx.z;
    const size_t bh = ((size_t)(b*Hv + h)) * Tv * 64;

    #pragma unroll
    for (int it = 0; it < 4; it++) {
        int i = it*256 + tid;
        int qrow = i >> 4, d4 = i & 15;
        float4 v = *(const float4*)(g_Q + bh + (size_t)(qt*64 + qrow)*64 + d4*4);
        Qt[(d4*4+0)*68 + qrow] = v.x; Qt[(d4*4+1)*68 + qrow] = v.y;
        Qt[(d4*4+2)*68 + qrow] = v.z; Qt[(d4*4+3)*68 + qrow] = v.w;
    }

    float tv[4][4]; int ti[4][4];
    #pragma unroll
    for (int q = 0; q < 4; q++)
        #pragma unroll
        for (int m = 0; m < 4; m++) { tv[q][m] = -3.0e38f; ti[q][m] = 0; }

    for (int kt = 0; kt <= qt; kt++) {
        __syncthreads();
        #pragma unroll
        for (int it = 0; it < 4; it++) {
            int i = it*256 + tid;
            int krow = i >> 4, d4 = i & 15;
            float4 v = *(const float4*)(g_K + bh + (size_t)(kt*64 + krow)*64 + d4*4);
            Kt[(d4*4+0)*68 + krow] = v.x; Kt[(d4*4+1)*68 + krow] = v.y;
            Kt[(d4*4+2)*68 + krow] = v.z; Kt[(d4*4+3)*68 + krow] = v.w;
        }
        __syncthreads();

        ull acc2[4][2];
        #pragma unroll
        for (int q = 0; q < 4; q++) { acc2[q][0] = 0ull; acc2[q][1] = 0ull; }

        #pragma unroll 8
        for (int d = 0; d < 64; d++) {
            float4 q4 = *(const float4*)&Qt[d*68 + qy*4];
            ulonglong2 k2 = *(const ulonglong2*)&Kt[d*68 + kx*4];
            ull qd0 = pk2(q4.x, q4.x), qd1 = pk2(q4.y, q4.y);
            ull qd2 = pk2(q4.z, q4.z), qd3 = pk2(q4.w, q4.w);
            fma2(acc2[0][0], qd0, k2.x); fma2(acc2[0][1], qd0, k2.y);
            fma2(acc2[1][0], qd1, k2.x); fma2(acc2[1][1], qd1, k2.y);
            fma2(acc2[2][0], qd2, k2.x); fma2(acc2[2][1], qd2, k2.y);
            fma2(acc2[3][0], qd3, k2.x); fma2(acc2[3][1], qd3, k2.y);
        }
        float acc[4][4];
        #pragma unroll
        for (int q = 0; q < 4; q++) {
            upk(acc2[q][0], acc[q][0], acc[q][1]);
            upk(acc2[q][1], acc[q][2], acc[q][3]);
        }

        #pragma unroll
        for (int q = 0; q < 4; q++) {
            int iglob = qt*64 + qy*4 + q;
            #pragma unroll
            for (int j = 0; j < 4; j++) {
                int jglob = kt*64 + kx*4 + j;
                float s = acc[q][j] * 0.125f;
                if (jglob <= iglob && s > tv[q][3]) {
                    if (s > tv[q][1]) {
                        tv[q][3] = tv[q][2]; ti[q][3] = ti[q][2];
                        tv[q][2] = tv[q][1]; ti[q][2] = ti[q][1];
                        if (s > tv[q][0]) {
                            tv[q][1] = tv[q][0]; ti[q][1] = ti[q][0];
                            tv[q][0] = s; ti[q][0] = jglob;
                        } else { tv[q][1] = s; ti[q][1] = jglob; }
                    } else {
                        if (s > tv[q][2]) {
                            tv[q][3] = tv[q][2]; ti[q][3] = ti[q][2];
                            tv[q][2] = s; ti[q][2] = jglob;
                        } else { tv[q][3] = s; ti[q][3] = jglob; }
                    }
                }
            }
        }
    }

    #pragma unroll
    for (int msk = 1; msk <= 8; msk <<= 1) {
        #pragma unroll
        for (int q = 0; q < 4; q++) {
            float bvv[4]; int bii[4];
            #pragma unroll
            for (int r = 0; r < 4; r++) {
                bvv[r] = __shfl_xor_sync(0xffffffffu, tv[q][r], msk);
                bii[r] = __shfl_xor_sync(0xffffffffu, ti[q][r], msk);
            }
            float mv[4]; int mi[4];
            #pragma unroll
            for (int r = 0; r < 4; r++) {
                bool ta = tv[q][r] >= bvv[3-r];
                mv[r] = ta ? tv[q][r] : bvv[3-r];
                mi[r] = ta ? ti[q][r] : bii[3-r];
            }
            #define CEPAIR(x, y) do { if (mv[x] < mv[y]) { float tf=mv[x];mv[x]=mv[y];mv[y]=tf; int tn=mi[x];mi[x]=mi[y];mi[y]=tn; } } while (0)
            CEPAIR(0,2); CEPAIR(1,3); CEPAIR(0,1); CEPAIR(2,3);
            #undef CEPAIR
            #pragma unroll
            for (int r = 0; r < 4; r++) { tv[q][r] = mv[r]; ti[q][r] = mi[r]; }
        }
    }

    #pragma unroll
    for (int q = 0; q < 4; q++) {
        int iglob = qt*64 + qy*4 + q;
        int nz = Tv - (iglob + 1);
        int p = (tv[q][0] > 0.f) + (tv[q][1] > 0.f) + (tv[q][2] > 0.f) + (tv[q][3] > 0.f);
        float kth;
        if (p >= 4) kth = tv[q][3];
        else if (nz >= 4 - p) kth = 0.0f;
        else {
            int ix = 3 - nz;
            kth = (ix == 0) ? tv[q][0] : (ix == 1) ? tv[q][1] : (ix == 2) ? tv[q][2] : tv[q][3];
        }
        float a0 = 0.f, a1 = 0.f, a2 = 0.f, a3 = 0.f;
        #pragma unroll
        for (int m = 0; m < 4; m++) {
            float val = tv[q][m];
            if (val >= kth && val > -1.0e37f) {
                float w = tanhf(val);
                float4 vv = *(const float4*)(g_V + bh + (size_t)ti[q][m]*64 + kx*4);
                a0 += w*vv.x; a1 += w*vv.y; a2 += w*vv.z; a3 += w*vv.w;
            }
        }
        *(float4*)(g_Y + (size_t)(b*Tv + iglob)*Cv + h*64 + kx*4) =
            make_float4(a0, a1, a2, a3);
    }
}

extern "C" void kernel_launch(void* const* d_in, const int* in_sizes, int n_in,
                              void* d_out, int out_size)
{
    (void)in_sizes; (void)n_in; (void)out_size;
    const float* x  = (const float*)d_in[0];
    const float* Wq = (const float*)d_in[1];
    const float* Wk = (const float*)d_in[2];
    const float* Wv = (const float*)d_in[3];
    const float* Wp = (const float*)d_in[4];
    const float* qm = (const float*)d_in[5];
    float* out = (float*)d_out;

    dim3 blk(256);
    gemm_kernel<<<dim3(32, 6, 3), blk>>>(x, Wq, Wk, Wv, qm, nullptr, 0);
    attn_kernel<<<dim3(32, 12, 2), blk>>>();
    gemm_kernel<<<dim3(32, 6, 1), blk>>>(nullptr, Wp, Wp, Wp, qm, out, 3);
}